// round 1
// baseline (speedup 1.0000x reference)
#include <cuda_runtime.h>
#include <math.h>

// Problem constants
#define BB 8
#define SS 1024
#define DD 512
#define HH 8
#define DFF 2048
#define LL 4
#define DKH 64
#define MROWS (BB*SS)   // 8192

// ---------------- scratch (static device globals; no cudaMalloc allowed) ----
__device__ float g_x  [MROWS*DD];
__device__ float g_y  [MROWS*DD];
__device__ float g_x1 [MROWS*DD];
__device__ float g_qk [MROWS*DD];   // [B,H,S,DK]
__device__ float g_v  [MROWS*DD];   // [B,H,S,DK]
__device__ float g_att[MROWS*DD];   // [B,S,D]
__device__ float g_tmp[MROWS*DD];
__device__ float g_h  [MROWS*DFF];

// ---------------- elementwise: out = in + pe (pe broadcast over batch) ------
__global__ __launch_bounds__(256) void addpe_kernel(const float* __restrict__ in,
                                                    const float* __restrict__ pe,
                                                    float* __restrict__ out) {
    int i4 = blockIdx.x * blockDim.x + threadIdx.x;      // float4 index
    const float4 a = ((const float4*)in)[i4];
    const float4 p = ((const float4*)pe)[i4 & (SS*DD/4 - 1)];
    float4 r; r.x=a.x+p.x; r.y=a.y+p.y; r.z=a.z+p.z; r.w=a.w+p.w;
    ((float4*)out)[i4] = r;
}

// ---------------- SGEMM: C = op(A[MxK] @ W[KxN] + bias) ---------------------
// MODE 0: plain   MODE 1: ReLU   MODE 2: head layout [B,H,S,DK]
template<int MODE>
__global__ __launch_bounds__(256) void sgemm_kernel(const float* __restrict__ A,
                                                    const float* __restrict__ W,
                                                    const float* __restrict__ bias,
                                                    float* __restrict__ C,
                                                    int M, int N, int K) {
    __shared__ float As[16][132];   // [k][m], padded
    __shared__ float Bs[16][68];    // [k][n], padded
    const int t  = threadIdx.x;
    const int tx = t & 15;          // n-group (4 cols)
    const int ty = t >> 4;          // m-group (8 rows)
    const int mBase = blockIdx.y * 128;
    const int nBase = blockIdx.x * 64;

    float acc[8][4];
    #pragma unroll
    for (int i = 0; i < 8; i++)
        #pragma unroll
        for (int j = 0; j < 4; j++) acc[i][j] = 0.f;

    for (int k0 = 0; k0 < K; k0 += 16) {
        // load A tile 128x16 (transposed into As[k][m])
        #pragma unroll
        for (int j = 0; j < 2; j++) {
            int p  = t + 256 * j;
            int m  = p >> 2, kq = p & 3;
            float4 av = *(const float4*)&A[(size_t)(mBase + m) * K + k0 + kq * 4];
            As[kq*4+0][m] = av.x; As[kq*4+1][m] = av.y;
            As[kq*4+2][m] = av.z; As[kq*4+3][m] = av.w;
        }
        // load B tile 16x64
        {
            int kk = t >> 4, nq = t & 15;
            float4 bv4 = *(const float4*)&W[(size_t)(k0 + kk) * N + nBase + nq * 4];
            *(float4*)&Bs[kk][nq * 4] = bv4;
        }
        __syncthreads();
        #pragma unroll
        for (int kk = 0; kk < 16; kk++) {
            float4 a0 = *(const float4*)&As[kk][ty * 8];
            float4 a1 = *(const float4*)&As[kk][ty * 8 + 4];
            float4 b0 = *(const float4*)&Bs[kk][tx * 4];
            float am[8] = {a0.x,a0.y,a0.z,a0.w,a1.x,a1.y,a1.z,a1.w};
            float bn[4] = {b0.x,b0.y,b0.z,b0.w};
            #pragma unroll
            for (int ii = 0; ii < 8; ii++)
                #pragma unroll
                for (int jj = 0; jj < 4; jj++)
                    acc[ii][jj] += am[ii] * bn[jj];
        }
        __syncthreads();
    }

    const float4 bv = *(const float4*)&bias[nBase + tx * 4];
    #pragma unroll
    for (int ii = 0; ii < 8; ii++) {
        int m = mBase + ty * 8 + ii;
        float4 r;
        r.x = acc[ii][0] + bv.x; r.y = acc[ii][1] + bv.y;
        r.z = acc[ii][2] + bv.z; r.w = acc[ii][3] + bv.w;
        if (MODE == 1) {
            r.x = fmaxf(r.x, 0.f); r.y = fmaxf(r.y, 0.f);
            r.z = fmaxf(r.z, 0.f); r.w = fmaxf(r.w, 0.f);
        }
        if (MODE == 2) {
            int b = m >> 10, s = m & 1023;
            int n = nBase + tx * 4;
            int h = n >> 6, dk = n & 63;
            *(float4*)&C[((size_t)(b * HH + h) * SS + s) * DKH + dk] = r;
        } else {
            *(float4*)&C[(size_t)m * N + nBase + tx * 4] = r;
        }
    }
}

// ---------------- strictly-causal flash attention, q==k ---------------------
// qk, v in [B,H,S,64]; out in [B,S,512]. One warp per query row; 8 rows/block.
__global__ __launch_bounds__(256) void attn_kernel(const float* __restrict__ qk,
                                                   const float* __restrict__ v,
                                                   float* __restrict__ out) {
    __shared__ float kst[64][65];   // [d][j]  (transposed, padded)
    __shared__ float vs [64][64];   // [j][d]
    __shared__ float qs [8][64];
    __shared__ float ps [8][64];

    const int t  = threadIdx.x;
    const int w  = t >> 5;
    const int l  = t & 31;
    const int bh = blockIdx.y;
    const int i0 = blockIdx.x * 8;
    const float* kbase = qk + (size_t)bh * SS * DKH;
    const float* vbase = v  + (size_t)bh * SS * DKH;

    // load the 8 query rows (warp w loads row w)
    {
        float2 qv = *(const float2*)&kbase[(size_t)(i0 + w) * DKH + l * 2];
        *(float2*)&qs[w][l * 2] = qv;
    }

    const int i = i0 + w;
    float m = -1e30f, lsum = 0.f, o0 = 0.f, o1 = 0.f;
    const int ntiles = (i0 + 7 + 63) >> 6;   // keys needed: j < i0+7

    for (int jt = 0; jt < ntiles; jt++) {
        const int j0 = jt * 64;
        __syncthreads();                     // prev tile consumed / qs visible
        #pragma unroll
        for (int it = 0; it < 4; it++) {
            int p = t + 256 * it;
            int j = p >> 4, dq = p & 15;
            float4 kv = *(const float4*)&kbase[(size_t)(j0 + j) * DKH + dq * 4];
            kst[dq*4+0][j] = kv.x; kst[dq*4+1][j] = kv.y;
            kst[dq*4+2][j] = kv.z; kst[dq*4+3][j] = kv.w;
            float4 vv = *(const float4*)&vbase[(size_t)(j0 + j) * DKH + dq * 4];
            *(float4*)&vs[j][dq * 4] = vv;
        }
        __syncthreads();

        if (j0 < i) {                        // warp-uniform
            float s0 = 0.f, s1 = 0.f;
            #pragma unroll 8
            for (int d = 0; d < 64; d++) {
                float qd = qs[w][d];
                s0 += qd * kst[d][l];
                s1 += qd * kst[d][l + 32];
            }
            const bool v0 = (j0 + l)      < i;
            const bool v1 = (j0 + 32 + l) < i;
            s0 = v0 ? s0 * 0.125f : -1e30f;
            s1 = v1 ? s1 * 0.125f : -1e30f;
            float smax = fmaxf(s0, s1);
            #pragma unroll
            for (int off = 16; off; off >>= 1)
                smax = fmaxf(smax, __shfl_xor_sync(0xffffffffu, smax, off));
            const float mnew = fmaxf(m, smax);
            const float corr = __expf(m - mnew);
            const float p0 = v0 ? __expf(s0 - mnew) : 0.f;
            const float p1 = v1 ? __expf(s1 - mnew) : 0.f;
            float psum = p0 + p1;
            #pragma unroll
            for (int off = 16; off; off >>= 1)
                psum += __shfl_xor_sync(0xffffffffu, psum, off);
            lsum = lsum * corr + psum;
            o0 *= corr; o1 *= corr;
            m = mnew;
            ps[w][l] = p0; ps[w][l + 32] = p1;
            __syncwarp();
            const int nvalid = min(64, i - j0);
            for (int jj = 0; jj < nvalid; jj++) {
                float p = ps[w][jj];
                float2 vv = *(const float2*)&vs[jj][l * 2];
                o0 += p * vv.x; o1 += p * vv.y;
            }
        }
    }

    const float inv = (lsum > 0.f) ? 1.f / lsum : 0.f;   // row 0 -> zeros
    o0 *= inv; o1 *= inv;
    const int b = bh >> 3, h = bh & 7;
    float2 res; res.x = o0; res.y = o1;
    *(float2*)&out[((size_t)(b * SS + i)) * DD + h * DKH + l * 2] = res;
}

// ---------------- layernorm: out = LN(a + b) * gamma + beta -----------------
__global__ __launch_bounds__(128) void ln_kernel(const float* __restrict__ a,
                                                 const float* __restrict__ b,
                                                 const float* __restrict__ g,
                                                 const float* __restrict__ bt,
                                                 float* __restrict__ out) {
    __shared__ float red1[4], red2[4];
    const int r = blockIdx.x, t = threadIdx.x;
    const int w = t >> 5, l = t & 31;
    float4 za = *(const float4*)&a[(size_t)r * DD + t * 4];
    float4 zb = *(const float4*)&b[(size_t)r * DD + t * 4];
    float z0 = za.x + zb.x, z1 = za.y + zb.y, z2 = za.z + zb.z, z3 = za.w + zb.w;

    float s = z0 + z1 + z2 + z3;
    #pragma unroll
    for (int off = 16; off; off >>= 1) s += __shfl_xor_sync(0xffffffffu, s, off);
    if (l == 0) red1[w] = s;
    __syncthreads();
    const float mean = (red1[0] + red1[1] + red1[2] + red1[3]) * (1.f / DD);

    float d0 = z0 - mean, d1 = z1 - mean, d2 = z2 - mean, d3 = z3 - mean;
    float sq = d0*d0 + d1*d1 + d2*d2 + d3*d3;
    #pragma unroll
    for (int off = 16; off; off >>= 1) sq += __shfl_xor_sync(0xffffffffu, sq, off);
    if (l == 0) red2[w] = sq;
    __syncthreads();
    const float var = (red2[0] + red2[1] + red2[2] + red2[3]) * (1.f / DD);
    const float rstd = rsqrtf(var + 1e-5f);

    float4 gg = *(const float4*)&g[t * 4];
    float4 bb = *(const float4*)&bt[t * 4];
    float4 o;
    o.x = d0 * rstd * gg.x + bb.x;
    o.y = d1 * rstd * gg.y + bb.y;
    o.z = d2 * rstd * gg.z + bb.z;
    o.w = d3 * rstd * gg.w + bb.w;
    *(float4*)&out[(size_t)r * DD + t * 4] = o;
}

// ---------------- orchestration ---------------------------------------------
extern "C" void kernel_launch(void* const* d_in, const int* in_sizes, int n_in,
                              void* d_out, int out_size) {
    const float* q_embed = (const float*)d_in[0];
    const float* qa_embed= (const float*)d_in[1];
    const float* pe      = (const float*)d_in[2];
    const float* Wk      = (const float*)d_in[3];
    const float* bk      = (const float*)d_in[4];
    const float* Wv      = (const float*)d_in[5];
    const float* bv      = (const float*)d_in[6];
    const float* Wo      = (const float*)d_in[7];
    const float* bo      = (const float*)d_in[8];
    const float* ln1_s   = (const float*)d_in[9];
    const float* ln1_b   = (const float*)d_in[10];
    const float* W1      = (const float*)d_in[11];
    const float* b1      = (const float*)d_in[12];
    const float* W2      = (const float*)d_in[13];
    const float* b2      = (const float*)d_in[14];
    const float* ln2_s   = (const float*)d_in[15];
    const float* ln2_b   = (const float*)d_in[16];
    float* outp = (float*)d_out;

    float *x, *y, *x1, *qkb, *vb, *att, *tmp, *hb;
    cudaGetSymbolAddress((void**)&x,   g_x);
    cudaGetSymbolAddress((void**)&y,   g_y);
    cudaGetSymbolAddress((void**)&x1,  g_x1);
    cudaGetSymbolAddress((void**)&qkb, g_qk);
    cudaGetSymbolAddress((void**)&vb,  g_v);
    cudaGetSymbolAddress((void**)&att, g_att);
    cudaGetSymbolAddress((void**)&tmp, g_tmp);
    cudaGetSymbolAddress((void**)&hb,  g_h);

    const int n4 = MROWS * DD / 4;
    addpe_kernel<<<n4 / 256, 256>>>(q_embed,  pe, x);
    addpe_kernel<<<n4 / 256, 256>>>(qa_embed, pe, y);

    dim3 gProj(DD / 64,  MROWS / 128);   // (8, 64)
    dim3 gFfn1(DFF / 64, MROWS / 128);   // (32, 64)
    dim3 gAttn(SS / 8, BB * HH);         // (128, 64)

    for (int l = 0; l < LL; l++) {
        const float* wk = Wk + (size_t)l * DD * DD;
        const float* wv = Wv + (size_t)l * DD * DD;
        const float* wo = Wo + (size_t)l * DD * DD;
        const float* w1 = W1 + (size_t)l * DD * DFF;
        const float* w2 = W2 + (size_t)l * DFF * DD;

        // q == k (kq_same): single projection
        sgemm_kernel<2><<<gProj, 256>>>(x, wk, bk + l * DD, qkb, MROWS, DD, DD);
        sgemm_kernel<2><<<gProj, 256>>>(y, wv, bv + l * DD, vb,  MROWS, DD, DD);
        attn_kernel<<<gAttn, 256>>>(qkb, vb, att);
        sgemm_kernel<0><<<gProj, 256>>>(att, wo, bo + l * DD, tmp, MROWS, DD, DD);
        ln_kernel<<<MROWS, 128>>>(x, tmp, ln1_s + l * DD, ln1_b + l * DD, x1);
        sgemm_kernel<1><<<gFfn1, 256>>>(x1, w1, b1 + l * DFF, hb, MROWS, DFF, DD);
        sgemm_kernel<0><<<gProj, 256>>>(hb, w2, b2 + l * DD, tmp, MROWS, DD, DFF);
        float* dst = (l == LL - 1) ? outp : x;
        ln_kernel<<<MROWS, 128>>>(x1, tmp, ln2_s + l * DD, ln2_b + l * DD, dst);
    }
}

// round 3
// speedup vs baseline: 1.7866x; 1.7866x over previous
#include <cuda_runtime.h>
#include <math.h>
#include <stdint.h>

// Problem constants
#define BB 8
#define SS 1024
#define DD 512
#define HH 8
#define DFF 2048
#define LL 4
#define DKH 64
#define MROWS (BB*SS)   // 8192

// ---------------- scratch (static device globals; no cudaMalloc allowed) ----
__device__ float g_x  [MROWS*DD];
__device__ float g_y  [MROWS*DD];
__device__ float g_x1 [MROWS*DD];
__device__ float g_qk [MROWS*DD];   // [B,H,S,DK]
__device__ float g_v  [MROWS*DD];   // [B,H,S,DK]
__device__ float g_att[MROWS*DD];   // [B,S,D]
__device__ float g_tmp[MROWS*DD];
__device__ float g_h  [MROWS*DFF];
// transposed weights [N,K]
__device__ float g_wkT[DD*DD];
__device__ float g_wvT[DD*DD];
__device__ float g_woT[DD*DD];
__device__ float g_w1T[DFF*DD];
__device__ float g_w2T[DD*DFF];

// ==================== helpers ====================
__device__ __forceinline__ uint32_t smem_u32(const void* p) {
    uint32_t a;
    asm("{ .reg .u64 t; cvta.to.shared.u64 t, %1; cvt.u32.u64 %0, t; }"
        : "=r"(a) : "l"(p));
    return a;
}

__device__ __forceinline__ void cp_async16(uint32_t dst, const void* src) {
    asm volatile("cp.async.cg.shared.global [%0], [%1], 16;"
                 :: "r"(dst), "l"(src) : "memory");
}
__device__ __forceinline__ void cp_commit() {
    asm volatile("cp.async.commit_group;" ::: "memory");
}
template<int N>
__device__ __forceinline__ void cp_wait() {
    asm volatile("cp.async.wait_group %0;" :: "n"(N) : "memory");
}

__device__ __forceinline__ void ldsm_x4(uint32_t addr, uint32_t& r0, uint32_t& r1,
                                        uint32_t& r2, uint32_t& r3) {
    asm volatile("ldmatrix.sync.aligned.m8n8.x4.shared.b16 {%0,%1,%2,%3}, [%4];"
                 : "=r"(r0), "=r"(r1), "=r"(r2), "=r"(r3) : "r"(addr));
}

__device__ __forceinline__ void mma_tf32(float& d0, float& d1, float& d2, float& d3,
                                         uint32_t a0, uint32_t a1, uint32_t a2, uint32_t a3,
                                         uint32_t b0, uint32_t b1) {
    asm volatile(
        "mma.sync.aligned.m16n8k8.row.col.f32.tf32.tf32.f32 "
        "{%0,%1,%2,%3}, {%4,%5,%6,%7}, {%8,%9}, {%0,%1,%2,%3};"
        : "+f"(d0), "+f"(d1), "+f"(d2), "+f"(d3)
        : "r"(a0), "r"(a1), "r"(a2), "r"(a3), "r"(b0), "r"(b1));
}

__device__ __forceinline__ uint32_t sw128(uint32_t off) {
    return off ^ ((off >> 3) & 0x70);
}

// ==================== tf32 mma.sync GEMM ====================
// C[M,N] = op(A[M,K] @ Bt[N,K]^T + bias). Tile 128x128, K-chunk 32.
// 256 thr = 8 warps, warp grid 2(M) x 4(N): each warp 64x32 = 4x4 m16n8k8.
// MODE 0: plain, 1: ReLU, 2: head layout [B,H,S,DK].
#define TILE_M 128
#define TILE_N 128
#define CHUNK_K 32
#define SMA_SZ (TILE_M * CHUNK_K * 4)    // 16384
#define SMB_SZ (TILE_N * CHUNK_K * 4)    // 16384
#define STAGE_SZ (SMA_SZ + SMB_SZ)
#define SM_TOTAL (2 * STAGE_SZ)          // 65536

__device__ __forceinline__ void issue_chunk(uint32_t sA, uint32_t sB,
                                            const float* __restrict__ Ab,
                                            const float* __restrict__ Bb,
                                            int ldA, int ldB, int tid) {
    #pragma unroll
    for (int j = 0; j < 4; j++) {
        int p = tid + 256 * j;           // 0..1023
        int row = p >> 3, seg = p & 7;
        cp_async16(sA + sw128(row * 128 + seg * 16), Ab + (size_t)row * ldA + seg * 4);
    }
    #pragma unroll
    for (int j = 0; j < 4; j++) {
        int p = tid + 256 * j;
        int row = p >> 3, seg = p & 7;
        cp_async16(sB + sw128(row * 128 + seg * 16), Bb + (size_t)row * ldB + seg * 4);
    }
}

template<int MODE>
__global__ void __launch_bounds__(256, 2) tc_gemm(const float* __restrict__ A,
                                                  const float* __restrict__ Bt,
                                                  const float* __restrict__ bias,
                                                  float* __restrict__ C,
                                                  int M, int N, int K) {
    extern __shared__ char smem[];
    const uint32_t sb = smem_u32(smem);
    const int tid  = threadIdx.x;
    const int wid  = tid >> 5, lane = tid & 31;
    const int wm   = wid & 1;            // M half  (64 rows)
    const int wn   = wid >> 1;           // N quarter (32 cols)
    const int mBase = blockIdx.y * TILE_M;
    const int nBase = blockIdx.x * TILE_N;

    const float* Ab = A  + (size_t)mBase * K;
    const float* Bb = Bt + (size_t)nBase * K;
    const int nc = K / CHUNK_K;

    float acc[4][4][4];
    #pragma unroll
    for (int i = 0; i < 4; i++)
        #pragma unroll
        for (int j = 0; j < 4; j++)
            #pragma unroll
            for (int q = 0; q < 4; q++) acc[i][j][q] = 0.f;

    // precompute ldmatrix lane addresses (offsets within a stage)
    // A: row = wm*64 + mt*16 + (lane&15), seg = ks*2 + (lane>>4)
    const int aRow = wm * 64 + (lane & 15);
    const int aSegOff = (lane >> 4);
    // B: matrix = lane>>3; row = wn*32 + pair*16 + (matrix>>1)*8 + (lane&7)
    //    seg = ks*2 + (matrix&1)
    const int bMat = lane >> 3;
    const int bRow = wn * 32 + ((bMat >> 1) << 3) + (lane & 7);
    const int bSegOff = (bMat & 1);

    issue_chunk(sb, sb + SMA_SZ, Ab, Bb, K, K, tid);
    cp_commit();

    for (int c = 0; c < nc; c++) {
        const uint32_t st = sb + (c & 1) * STAGE_SZ;
        if (c + 1 < nc) {
            const uint32_t sn = sb + ((c + 1) & 1) * STAGE_SZ;
            issue_chunk(sn, sn + SMA_SZ,
                        Ab + (size_t)(c + 1) * CHUNK_K,
                        Bb + (size_t)(c + 1) * CHUNK_K, K, K, tid);
            cp_commit();
            cp_wait<1>();
        } else {
            cp_wait<0>();
        }
        __syncthreads();

        const uint32_t sA = st, sB = st + SMA_SZ;
        #pragma unroll
        for (int ks = 0; ks < 4; ks++) {
            uint32_t aF[4][4];
            #pragma unroll
            for (int mt = 0; mt < 4; mt++) {
                uint32_t off = (aRow + mt * 16) * 128 + (ks * 2 + aSegOff) * 16;
                ldsm_x4(sA + sw128(off), aF[mt][0], aF[mt][1], aF[mt][2], aF[mt][3]);
            }
            uint32_t bF[4][2];
            #pragma unroll
            for (int pair = 0; pair < 2; pair++) {
                uint32_t off = (bRow + pair * 16) * 128 + (ks * 2 + bSegOff) * 16;
                uint32_t r0, r1, r2, r3;
                ldsm_x4(sB + sw128(off), r0, r1, r2, r3);
                bF[pair * 2 + 0][0] = r0; bF[pair * 2 + 0][1] = r1;
                bF[pair * 2 + 1][0] = r2; bF[pair * 2 + 1][1] = r3;
            }
            #pragma unroll
            for (int mt = 0; mt < 4; mt++)
                #pragma unroll
                for (int nt = 0; nt < 4; nt++)
                    mma_tf32(acc[mt][nt][0], acc[mt][nt][1], acc[mt][nt][2], acc[mt][nt][3],
                             aF[mt][0], aF[mt][1], aF[mt][2], aF[mt][3],
                             bF[nt][0], bF[nt][1]);
        }
        __syncthreads();
    }

    // epilogue: thread owns (row = base + t/4 (+8), col = base + (t%4)*2 (+1))
    const int rBase = mBase + wm * 64 + (lane >> 2);
    const int cBase = nBase + wn * 32 + (lane & 3) * 2;
    #pragma unroll
    for (int mt = 0; mt < 4; mt++) {
        #pragma unroll
        for (int nt = 0; nt < 4; nt++) {
            const int col = cBase + nt * 8;
            const float bx = bias[col], by = bias[col + 1];
            #pragma unroll
            for (int half = 0; half < 2; half++) {
                const int row = rBase + mt * 16 + half * 8;
                float2 o;
                o.x = acc[mt][nt][half * 2 + 0] + bx;
                o.y = acc[mt][nt][half * 2 + 1] + by;
                if (MODE == 1) { o.x = fmaxf(o.x, 0.f); o.y = fmaxf(o.y, 0.f); }
                if (MODE == 2) {
                    int bi = row >> 10, s = row & 1023;
                    int h = col >> 6, dk = col & 63;
                    *(float2*)&C[((size_t)(bi * HH + h) * SS + s) * DKH + dk] = o;
                } else {
                    *(float2*)&C[(size_t)row * N + col] = o;
                }
            }
        }
    }
}

// ==================== transpose: dst[C,R] = src[R,C]^T ====================
__global__ __launch_bounds__(256) void transpose_kernel(const float* __restrict__ src,
                                                        float* __restrict__ dst,
                                                        int R, int C) {
    __shared__ float tile[32][33];
    const int c0 = blockIdx.x * 32, r0 = blockIdx.y * 32;
    const int x = threadIdx.x, y = threadIdx.y;   // 32 x 8
    #pragma unroll
    for (int j = 0; j < 32; j += 8)
        tile[y + j][x] = src[(size_t)(r0 + y + j) * C + c0 + x];
    __syncthreads();
    #pragma unroll
    for (int j = 0; j < 32; j += 8)
        dst[(size_t)(c0 + y + j) * R + r0 + x] = tile[x][y + j];
}

// ---------------- elementwise: out = in + pe (pe broadcast over batch) ------
__global__ __launch_bounds__(256) void addpe_kernel(const float* __restrict__ in,
                                                    const float* __restrict__ pe,
                                                    float* __restrict__ out) {
    int i4 = blockIdx.x * blockDim.x + threadIdx.x;
    const float4 a = ((const float4*)in)[i4];
    const float4 p = ((const float4*)pe)[i4 & (SS*DD/4 - 1)];
    float4 r; r.x=a.x+p.x; r.y=a.y+p.y; r.z=a.z+p.z; r.w=a.w+p.w;
    ((float4*)out)[i4] = r;
}

// ---------------- strictly-causal flash attention, q==k ---------------------
__global__ __launch_bounds__(256) void attn_kernel(const float* __restrict__ qk,
                                                   const float* __restrict__ v,
                                                   float* __restrict__ out) {
    __shared__ float kst[64][65];
    __shared__ float vs [64][64];
    __shared__ float qs [8][64];
    __shared__ float ps [8][64];

    const int t  = threadIdx.x;
    const int w  = t >> 5;
    const int l  = t & 31;
    const int bh = blockIdx.y;
    const int i0 = blockIdx.x * 8;
    const float* kbase = qk + (size_t)bh * SS * DKH;
    const float* vbase = v  + (size_t)bh * SS * DKH;

    {
        float2 qv = *(const float2*)&kbase[(size_t)(i0 + w) * DKH + l * 2];
        *(float2*)&qs[w][l * 2] = qv;
    }

    const int i = i0 + w;
    float m = -1e30f, lsum = 0.f, o0 = 0.f, o1 = 0.f;
    const int ntiles = (i0 + 7 + 63) >> 6;

    for (int jt = 0; jt < ntiles; jt++) {
        const int j0 = jt * 64;
        __syncthreads();
        #pragma unroll
        for (int it = 0; it < 4; it++) {
            int p = t + 256 * it;
            int j = p >> 4, dq = p & 15;
            float4 kv = *(const float4*)&kbase[(size_t)(j0 + j) * DKH + dq * 4];
            kst[dq*4+0][j] = kv.x; kst[dq*4+1][j] = kv.y;
            kst[dq*4+2][j] = kv.z; kst[dq*4+3][j] = kv.w;
            float4 vv = *(const float4*)&vbase[(size_t)(j0 + j) * DKH + dq * 4];
            *(float4*)&vs[j][dq * 4] = vv;
        }
        __syncthreads();

        if (j0 < i) {
            float s0 = 0.f, s1 = 0.f;
            #pragma unroll 8
            for (int d = 0; d < 64; d++) {
                float qd = qs[w][d];
                s0 += qd * kst[d][l];
                s1 += qd * kst[d][l + 32];
            }
            const bool v0 = (j0 + l)      < i;
            const bool v1 = (j0 + 32 + l) < i;
            s0 = v0 ? s0 * 0.125f : -1e30f;
            s1 = v1 ? s1 * 0.125f : -1e30f;
            float smax = fmaxf(s0, s1);
            #pragma unroll
            for (int off = 16; off; off >>= 1)
                smax = fmaxf(smax, __shfl_xor_sync(0xffffffffu, smax, off));
            const float mnew = fmaxf(m, smax);
            const float corr = __expf(m - mnew);
            const float p0 = v0 ? __expf(s0 - mnew) : 0.f;
            const float p1 = v1 ? __expf(s1 - mnew) : 0.f;
            float psum = p0 + p1;
            #pragma unroll
            for (int off = 16; off; off >>= 1)
                psum += __shfl_xor_sync(0xffffffffu, psum, off);
            lsum = lsum * corr + psum;
            o0 *= corr; o1 *= corr;
            m = mnew;
            ps[w][l] = p0; ps[w][l + 32] = p1;
            __syncwarp();
            const int nvalid = min(64, i - j0);
            for (int jj = 0; jj < nvalid; jj++) {
                float p = ps[w][jj];
                float2 vv = *(const float2*)&vs[jj][l * 2];
                o0 += p * vv.x; o1 += p * vv.y;
            }
        }
    }

    const float inv = (lsum > 0.f) ? 1.f / lsum : 0.f;
    o0 *= inv; o1 *= inv;
    const int b = bh >> 3, h = bh & 7;
    float2 res; res.x = o0; res.y = o1;
    *(float2*)&out[((size_t)(b * SS + i)) * DD + h * DKH + l * 2] = res;
}

// ---------------- layernorm: out = LN(a + b) * gamma + beta -----------------
__global__ __launch_bounds__(128) void ln_kernel(const float* __restrict__ a,
                                                 const float* __restrict__ b,
                                                 const float* __restrict__ g,
                                                 const float* __restrict__ bt,
                                                 float* __restrict__ out) {
    __shared__ float red1[4], red2[4];
    const int r = blockIdx.x, t = threadIdx.x;
    const int w = t >> 5, l = t & 31;
    float4 za = *(const float4*)&a[(size_t)r * DD + t * 4];
    float4 zb = *(const float4*)&b[(size_t)r * DD + t * 4];
    float z0 = za.x + zb.x, z1 = za.y + zb.y, z2 = za.z + zb.z, z3 = za.w + zb.w;

    float s = z0 + z1 + z2 + z3;
    #pragma unroll
    for (int off = 16; off; off >>= 1) s += __shfl_xor_sync(0xffffffffu, s, off);
    if (l == 0) red1[w] = s;
    __syncthreads();
    const float mean = (red1[0] + red1[1] + red1[2] + red1[3]) * (1.f / DD);

    float d0 = z0 - mean, d1 = z1 - mean, d2 = z2 - mean, d3 = z3 - mean;
    float sq = d0*d0 + d1*d1 + d2*d2 + d3*d3;
    #pragma unroll
    for (int off = 16; off; off >>= 1) sq += __shfl_xor_sync(0xffffffffu, sq, off);
    if (l == 0) red2[w] = sq;
    __syncthreads();
    const float var = (red2[0] + red2[1] + red2[2] + red2[3]) * (1.f / DD);
    const float rstd = rsqrtf(var + 1e-5f);

    float4 gg = *(const float4*)&g[t * 4];
    float4 bb = *(const float4*)&bt[t * 4];
    float4 o;
    o.x = d0 * rstd * gg.x + bb.x;
    o.y = d1 * rstd * gg.y + bb.y;
    o.z = d2 * rstd * gg.z + bb.z;
    o.w = d3 * rstd * gg.w + bb.w;
    *(float4*)&out[(size_t)r * DD + t * 4] = o;
}

// ---------------- orchestration ---------------------------------------------
extern "C" void kernel_launch(void* const* d_in, const int* in_sizes, int n_in,
                              void* d_out, int out_size) {
    const float* q_embed = (const float*)d_in[0];
    const float* qa_embed= (const float*)d_in[1];
    const float* pe      = (const float*)d_in[2];
    const float* Wk      = (const float*)d_in[3];
    const float* bk      = (const float*)d_in[4];
    const float* Wv      = (const float*)d_in[5];
    const float* bv      = (const float*)d_in[6];
    const float* Wo      = (const float*)d_in[7];
    const float* bo      = (const float*)d_in[8];
    const float* ln1_s   = (const float*)d_in[9];
    const float* ln1_b   = (const float*)d_in[10];
    const float* W1      = (const float*)d_in[11];
    const float* b1      = (const float*)d_in[12];
    const float* W2      = (const float*)d_in[13];
    const float* b2      = (const float*)d_in[14];
    const float* ln2_s   = (const float*)d_in[15];
    const float* ln2_b   = (const float*)d_in[16];
    float* outp = (float*)d_out;

    float *x, *y, *x1, *qkb, *vb, *att, *tmp, *hb;
    float *wkT, *wvT, *woT, *w1T, *w2T;
    cudaGetSymbolAddress((void**)&x,   g_x);
    cudaGetSymbolAddress((void**)&y,   g_y);
    cudaGetSymbolAddress((void**)&x1,  g_x1);
    cudaGetSymbolAddress((void**)&qkb, g_qk);
    cudaGetSymbolAddress((void**)&vb,  g_v);
    cudaGetSymbolAddress((void**)&att, g_att);
    cudaGetSymbolAddress((void**)&tmp, g_tmp);
    cudaGetSymbolAddress((void**)&hb,  g_h);
    cudaGetSymbolAddress((void**)&wkT, g_wkT);
    cudaGetSymbolAddress((void**)&wvT, g_wvT);
    cudaGetSymbolAddress((void**)&woT, g_woT);
    cudaGetSymbolAddress((void**)&w1T, g_w1T);
    cudaGetSymbolAddress((void**)&w2T, g_w2T);

    cudaFuncSetAttribute(tc_gemm<0>, cudaFuncAttributeMaxDynamicSharedMemorySize, SM_TOTAL);
    cudaFuncSetAttribute(tc_gemm<1>, cudaFuncAttributeMaxDynamicSharedMemorySize, SM_TOTAL);
    cudaFuncSetAttribute(tc_gemm<2>, cudaFuncAttributeMaxDynamicSharedMemorySize, SM_TOTAL);

    const int n4 = MROWS * DD / 4;
    addpe_kernel<<<n4 / 256, 256>>>(q_embed,  pe, x);
    addpe_kernel<<<n4 / 256, 256>>>(qa_embed, pe, y);

    dim3 tb(32, 8);
    dim3 gT_dd(DD / 32, DD / 32);
    dim3 gT_w1(DFF / 32, DD / 32);
    dim3 gT_w2(DD / 32, DFF / 32);

    dim3 gProj(DD / TILE_N,  MROWS / TILE_M);   // (4, 64)
    dim3 gFfn1(DFF / TILE_N, MROWS / TILE_M);   // (16, 64)
    dim3 gAttn(SS / 8, BB * HH);

    for (int l = 0; l < LL; l++) {
        const float* wk = Wk + (size_t)l * DD * DD;
        const float* wv = Wv + (size_t)l * DD * DD;
        const float* wo = Wo + (size_t)l * DD * DD;
        const float* w1 = W1 + (size_t)l * DD * DFF;
        const float* w2 = W2 + (size_t)l * DFF * DD;

        transpose_kernel<<<gT_dd, tb>>>(wk, wkT, DD, DD);
        transpose_kernel<<<gT_dd, tb>>>(wv, wvT, DD, DD);
        transpose_kernel<<<gT_dd, tb>>>(wo, woT, DD, DD);
        transpose_kernel<<<gT_w1, tb>>>(w1, w1T, DD, DFF);
        transpose_kernel<<<gT_w2, tb>>>(w2, w2T, DFF, DD);

        // q == k (kq_same): single projection
        tc_gemm<2><<<gProj, 256, SM_TOTAL>>>(x, wkT, bk + l * DD, qkb, MROWS, DD, DD);
        tc_gemm<2><<<gProj, 256, SM_TOTAL>>>(y, wvT, bv + l * DD, vb,  MROWS, DD, DD);
        attn_kernel<<<gAttn, 256>>>(qkb, vb, att);
        tc_gemm<0><<<gProj, 256, SM_TOTAL>>>(att, woT, bo + l * DD, tmp, MROWS, DD, DD);
        ln_kernel<<<MROWS, 128>>>(x, tmp, ln1_s + l * DD, ln1_b + l * DD, x1);
        tc_gemm<1><<<gFfn1, 256, SM_TOTAL>>>(x1, w1T, b1 + l * DFF, hb, MROWS, DFF, DD);
        tc_gemm<0><<<gProj, 256, SM_TOTAL>>>(hb, w2T, b2 + l * DD, tmp, MROWS, DD, DFF);
        float* dst = (l == LL - 1) ? outp : x;
        ln_kernel<<<MROWS, 128>>>(x1, tmp, ln2_s + l * DD, ln2_b + l * DD, dst);
    }
}

// round 4
// speedup vs baseline: 5.3159x; 2.9754x over previous
#include <cuda_runtime.h>
#include <math.h>
#include <stdint.h>

// Problem constants
#define BB 8
#define SS 1024
#define DD 512
#define HH 8
#define DFF 2048
#define LL 4
#define DKH 64
#define MROWS (BB*SS)   // 8192

// ---------------- scratch (static device globals) ---------------------------
__device__ float g_x   [MROWS*DD];
__device__ float g_xtf [MROWS*DD];
__device__ float g_y   [MROWS*DD];
__device__ float g_x1  [MROWS*DD];
__device__ float g_x1tf[MROWS*DD];
__device__ float g_qk  [MROWS*DD];   // [B,H,S,DK]  (tf32-rounded)
__device__ float g_vt  [MROWS*DD];   // [B,H,DK,S]  V^T (tf32-rounded)
__device__ float g_att [MROWS*DD];   // [B,S,D]     (tf32-rounded)
__device__ float g_tmp [MROWS*DD];
__device__ float g_h   [MROWS*DFF];
// transposed weights [N,K] (tf32-rounded)
__device__ float g_wkT[DD*DD];
__device__ float g_wvT[DD*DD];
__device__ float g_woT[DD*DD];
__device__ float g_w1T[DFF*DD];
__device__ float g_w2T[DD*DFF];

// ==================== helpers ====================
__device__ __forceinline__ uint32_t smem_u32(const void* p) {
    uint32_t a;
    asm("{ .reg .u64 t; cvta.to.shared.u64 t, %1; cvt.u32.u64 %0, t; }"
        : "=r"(a) : "l"(p));
    return a;
}
__device__ __forceinline__ void cp_async16(uint32_t dst, const void* src) {
    asm volatile("cp.async.cg.shared.global [%0], [%1], 16;"
                 :: "r"(dst), "l"(src) : "memory");
}
__device__ __forceinline__ void cp_commit() {
    asm volatile("cp.async.commit_group;" ::: "memory");
}
template<int N>
__device__ __forceinline__ void cp_wait() {
    asm volatile("cp.async.wait_group %0;" :: "n"(N) : "memory");
}
__device__ __forceinline__ void ldsm_x4(uint32_t addr, uint32_t& r0, uint32_t& r1,
                                        uint32_t& r2, uint32_t& r3) {
    asm volatile("ldmatrix.sync.aligned.m8n8.x4.shared.b16 {%0,%1,%2,%3}, [%4];"
                 : "=r"(r0), "=r"(r1), "=r"(r2), "=r"(r3) : "r"(addr));
}
__device__ __forceinline__ void mma_tf32(float& d0, float& d1, float& d2, float& d3,
                                         uint32_t a0, uint32_t a1, uint32_t a2, uint32_t a3,
                                         uint32_t b0, uint32_t b1) {
    asm volatile(
        "mma.sync.aligned.m16n8k8.row.col.f32.tf32.tf32.f32 "
        "{%0,%1,%2,%3}, {%4,%5,%6,%7}, {%8,%9}, {%0,%1,%2,%3};"
        : "+f"(d0), "+f"(d1), "+f"(d2), "+f"(d3)
        : "r"(a0), "r"(a1), "r"(a2), "r"(a3), "r"(b0), "r"(b1));
}
__device__ __forceinline__ uint32_t sw128(uint32_t off) {
    return off ^ ((off >> 3) & 0x70);
}
__device__ __forceinline__ float to_tf32(float x) {
    uint32_t u;
    asm("cvt.rna.tf32.f32 %0, %1;" : "=r"(u) : "f"(x));
    return __uint_as_float(u);
}
__device__ __forceinline__ float ex2f(float x) {
    float y;
    asm("ex2.approx.f32 %0, %1;" : "=f"(y) : "f"(x));
    return y;
}

// ==================== tf32 mma.sync GEMM ====================
// C[M,N] = op(A[M,K] @ Bt[N,K]^T + bias). Tile 128x128, K-chunk 32.
// MODE 0: plain, 1: ReLU+round, 2: head layout [B,H,S,DK]+round,
// MODE 3: V^T layout [B,H,DK,S]+round.
#define TILE_M 128
#define TILE_N 128
#define CHUNK_K 32
#define SMA_SZ (TILE_M * CHUNK_K * 4)
#define SMB_SZ (TILE_N * CHUNK_K * 4)
#define STAGE_SZ (SMA_SZ + SMB_SZ)
#define SM_TOTAL (2 * STAGE_SZ)

__device__ __forceinline__ void issue_chunk(uint32_t sA, uint32_t sB,
                                            const float* __restrict__ Ab,
                                            const float* __restrict__ Bb,
                                            int ldA, int ldB, int tid) {
    #pragma unroll
    for (int j = 0; j < 4; j++) {
        int p = tid + 256 * j;
        int row = p >> 3, seg = p & 7;
        cp_async16(sA + sw128(row * 128 + seg * 16), Ab + (size_t)row * ldA + seg * 4);
    }
    #pragma unroll
    for (int j = 0; j < 4; j++) {
        int p = tid + 256 * j;
        int row = p >> 3, seg = p & 7;
        cp_async16(sB + sw128(row * 128 + seg * 16), Bb + (size_t)row * ldB + seg * 4);
    }
}

template<int MODE>
__global__ void __launch_bounds__(256, 2) tc_gemm(const float* __restrict__ A,
                                                  const float* __restrict__ Bt,
                                                  const float* __restrict__ bias,
                                                  float* __restrict__ C,
                                                  int M, int N, int K) {
    extern __shared__ char smem[];
    const uint32_t sb = smem_u32(smem);
    const int tid  = threadIdx.x;
    const int wid  = tid >> 5, lane = tid & 31;
    const int wm   = wid & 1;
    const int wn   = wid >> 1;
    const int mBase = blockIdx.y * TILE_M;
    const int nBase = blockIdx.x * TILE_N;

    const float* Ab = A  + (size_t)mBase * K;
    const float* Bb = Bt + (size_t)nBase * K;
    const int nc = K / CHUNK_K;

    float acc[4][4][4];
    #pragma unroll
    for (int i = 0; i < 4; i++)
        #pragma unroll
        for (int j = 0; j < 4; j++)
            #pragma unroll
            for (int q = 0; q < 4; q++) acc[i][j][q] = 0.f;

    const int aRow = wm * 64 + (lane & 15);
    const int aSegOff = (lane >> 4);
    const int bMat = lane >> 3;
    const int bRow = wn * 32 + ((bMat >> 1) << 3) + (lane & 7);
    const int bSegOff = (bMat & 1);

    issue_chunk(sb, sb + SMA_SZ, Ab, Bb, K, K, tid);
    cp_commit();

    for (int c = 0; c < nc; c++) {
        const uint32_t st = sb + (c & 1) * STAGE_SZ;
        if (c + 1 < nc) {
            const uint32_t sn = sb + ((c + 1) & 1) * STAGE_SZ;
            issue_chunk(sn, sn + SMA_SZ,
                        Ab + (size_t)(c + 1) * CHUNK_K,
                        Bb + (size_t)(c + 1) * CHUNK_K, K, K, tid);
            cp_commit();
            cp_wait<1>();
        } else {
            cp_wait<0>();
        }
        __syncthreads();

        const uint32_t sA = st, sB = st + SMA_SZ;
        #pragma unroll
        for (int ks = 0; ks < 4; ks++) {
            uint32_t aF[4][4];
            #pragma unroll
            for (int mt = 0; mt < 4; mt++) {
                uint32_t off = (aRow + mt * 16) * 128 + (ks * 2 + aSegOff) * 16;
                ldsm_x4(sA + sw128(off), aF[mt][0], aF[mt][1], aF[mt][2], aF[mt][3]);
            }
            uint32_t bF[4][2];
            #pragma unroll
            for (int pair = 0; pair < 2; pair++) {
                uint32_t off = (bRow + pair * 16) * 128 + (ks * 2 + bSegOff) * 16;
                uint32_t r0, r1, r2, r3;
                ldsm_x4(sB + sw128(off), r0, r1, r2, r3);
                bF[pair * 2 + 0][0] = r0; bF[pair * 2 + 0][1] = r1;
                bF[pair * 2 + 1][0] = r2; bF[pair * 2 + 1][1] = r3;
            }
            #pragma unroll
            for (int mt = 0; mt < 4; mt++)
                #pragma unroll
                for (int nt = 0; nt < 4; nt++)
                    mma_tf32(acc[mt][nt][0], acc[mt][nt][1], acc[mt][nt][2], acc[mt][nt][3],
                             aF[mt][0], aF[mt][1], aF[mt][2], aF[mt][3],
                             bF[nt][0], bF[nt][1]);
        }
        __syncthreads();
    }

    const int rBase = mBase + wm * 64 + (lane >> 2);
    const int cBase = nBase + wn * 32 + (lane & 3) * 2;
    #pragma unroll
    for (int mt = 0; mt < 4; mt++) {
        #pragma unroll
        for (int nt = 0; nt < 4; nt++) {
            const int col = cBase + nt * 8;
            const float bx = bias[col], by = bias[col + 1];
            #pragma unroll
            for (int half = 0; half < 2; half++) {
                const int row = rBase + mt * 16 + half * 8;
                float2 o;
                o.x = acc[mt][nt][half * 2 + 0] + bx;
                o.y = acc[mt][nt][half * 2 + 1] + by;
                if (MODE == 1) {
                    o.x = to_tf32(fmaxf(o.x, 0.f));
                    o.y = to_tf32(fmaxf(o.y, 0.f));
                }
                if (MODE == 2) {
                    int bi = row >> 10, s = row & 1023;
                    int h = col >> 6, dk = col & 63;
                    o.x = to_tf32(o.x); o.y = to_tf32(o.y);
                    *(float2*)&C[((size_t)(bi * HH + h) * SS + s) * DKH + dk] = o;
                } else if (MODE == 3) {
                    int bi = row >> 10, s = row & 1023;
                    int h = col >> 6, dk = col & 63;
                    float* base = &C[((size_t)(bi * HH + h) * DKH + dk) * SS + s];
                    base[0]  = to_tf32(o.x);
                    base[SS] = to_tf32(o.y);
                } else {
                    *(float2*)&C[(size_t)row * N + col] = o;
                }
            }
        }
    }
}

// ==================== TC flash attention (strictly causal, q==k) ============
// qk: [B,H,S,64] (tf32), vt: [B,H,64,S] (tf32), out: [B,S,512] (tf32-rounded)
// Grid (16, 64): CTA = (q-tile qt, bh). 128 threads = 4 warps x 16 rows.
#define AT_Q  0
#define AT_P  16384
#define AT_S0 32768
#define AT_STG 32768
#define AT_TOTAL 98304

__device__ __forceinline__ void attn_stage(uint32_t base, const float* kb,
                                           const float* vb, int j0, int tid) {
    #pragma unroll
    for (int j = 0; j < 8; j++) {
        int s = tid + 128 * j;
        int sub = s >> 9, row = (s >> 3) & 63, seg = s & 7;
        cp_async16(base + sub * 8192 + sw128(row * 128 + seg * 16),
                   kb + (size_t)(j0 + row) * DKH + sub * 32 + seg * 4);
    }
    #pragma unroll
    for (int j = 0; j < 8; j++) {
        int s = tid + 128 * j;
        int sub = s >> 9, row = (s >> 3) & 63, seg = s & 7;
        cp_async16(base + 16384 + sub * 8192 + sw128(row * 128 + seg * 16),
                   vb + (size_t)row * SS + j0 + sub * 32 + seg * 4);
    }
}

__global__ void __launch_bounds__(128, 2) attn_tc(const float* __restrict__ qk,
                                                  const float* __restrict__ vt,
                                                  float* __restrict__ out) {
    extern __shared__ char smem[];
    const uint32_t sb = smem_u32(smem);
    const int tid = threadIdx.x, lane = tid & 31, w = tid >> 5;
    const int qt = blockIdx.x, bh = blockIdx.y;
    const int i0 = qt * 64;
    const float* kb = qk + (size_t)bh * SS * DKH;
    const float* vb = vt + (size_t)bh * DKH * SS;
    const float QSCALE = 0.18033688011112042f;  // log2(e)/8

    // load Q (scaled + rounded) into SMEM
    #pragma unroll
    for (int j = 0; j < 8; j++) {
        int s = tid + 128 * j;
        int sub = s >> 9, row = (s >> 3) & 63, seg = s & 7;
        float4 v = *(const float4*)&kb[(size_t)(i0 + row) * DKH + sub * 32 + seg * 4];
        v.x = to_tf32(v.x * QSCALE); v.y = to_tf32(v.y * QSCALE);
        v.z = to_tf32(v.z * QSCALE); v.w = to_tf32(v.w * QSCALE);
        *(float4*)(smem + AT_Q + sub * 8192 + sw128(row * 128 + seg * 16)) = v;
    }
    attn_stage(sb + AT_S0, kb, vb, 0, tid);
    cp_commit();

    // per-thread fragment addressing (reused pattern, verified in GEMM)
    const int aRow = w * 16 + (lane & 15);
    const int aSegOff = (lane >> 4);
    const int bMat = lane >> 3;
    const int bRowL = ((bMat >> 1) << 3) + (lane & 7);
    const int bSegOff = (bMat & 1);

    const int r0 = i0 + w * 16 + (lane >> 2);   // absolute row, half 0
    float mh0 = -1e30f, mh1 = -1e30f, lh0 = 0.f, lh1 = 0.f;
    float o[8][4];
    #pragma unroll
    for (int nt = 0; nt < 8; nt++)
        #pragma unroll
        for (int q = 0; q < 4; q++) o[nt][q] = 0.f;

    for (int jt = 0; jt <= qt; jt++) {
        if (jt < qt) {
            attn_stage(sb + AT_S0 + ((jt + 1) & 1) * AT_STG, kb, vb, (jt + 1) * 64, tid);
            cp_commit();
            cp_wait<1>();
        } else {
            cp_wait<0>();
        }
        __syncthreads();
        const uint32_t sK = sb + AT_S0 + (jt & 1) * AT_STG;
        const uint32_t sV = sK + 16384;
        const int j0 = jt * 64;

        // ---- scores S = Qs * K^T (in log2 domain) ----
        float s[8][4];
        #pragma unroll
        for (int nt = 0; nt < 8; nt++)
            #pragma unroll
            for (int q = 0; q < 4; q++) s[nt][q] = 0.f;

        #pragma unroll
        for (int ks = 0; ks < 8; ks++) {
            uint32_t a0, a1, a2, a3;
            uint32_t aoff = (ks >> 2) * 8192 +
                            sw128(aRow * 128 + ((ks & 3) * 2 + aSegOff) * 16);
            ldsm_x4(sb + AT_Q + aoff, a0, a1, a2, a3);
            #pragma unroll
            for (int pr = 0; pr < 4; pr++) {
                uint32_t boff = (ks >> 2) * 8192 +
                                sw128((pr * 16 + bRowL) * 128 + ((ks & 3) * 2 + bSegOff) * 16);
                uint32_t b0, b1, b2, b3;
                ldsm_x4(sK + boff, b0, b1, b2, b3);
                mma_tf32(s[pr*2][0], s[pr*2][1], s[pr*2][2], s[pr*2][3],
                         a0, a1, a2, a3, b0, b1);
                mma_tf32(s[pr*2+1][0], s[pr*2+1][1], s[pr*2+1][2], s[pr*2+1][3],
                         a0, a1, a2, a3, b2, b3);
            }
        }

        // ---- causal mask (only the diagonal tile) ----
        if (jt == qt) {
            #pragma unroll
            for (int nt = 0; nt < 8; nt++) {
                int jb = j0 + nt * 8 + 2 * (lane & 3);
                s[nt][0] = (jb     < r0    ) ? s[nt][0] : -1e30f;
                s[nt][1] = (jb + 1 < r0    ) ? s[nt][1] : -1e30f;
                s[nt][2] = (jb     < r0 + 8) ? s[nt][2] : -1e30f;
                s[nt][3] = (jb + 1 < r0 + 8) ? s[nt][3] : -1e30f;
            }
        }

        // ---- online softmax (base-2) ----
        float rm0 = -1e30f, rm1 = -1e30f;
        #pragma unroll
        for (int nt = 0; nt < 8; nt++) {
            rm0 = fmaxf(rm0, fmaxf(s[nt][0], s[nt][1]));
            rm1 = fmaxf(rm1, fmaxf(s[nt][2], s[nt][3]));
        }
        rm0 = fmaxf(rm0, __shfl_xor_sync(0xffffffffu, rm0, 1));
        rm0 = fmaxf(rm0, __shfl_xor_sync(0xffffffffu, rm0, 2));
        rm1 = fmaxf(rm1, __shfl_xor_sync(0xffffffffu, rm1, 1));
        rm1 = fmaxf(rm1, __shfl_xor_sync(0xffffffffu, rm1, 2));
        const float mn0 = fmaxf(mh0, rm0), mn1 = fmaxf(mh1, rm1);
        const float c0 = ex2f(mh0 - mn0), c1 = ex2f(mh1 - mn1);
        mh0 = mn0; mh1 = mn1;

        float ps0 = 0.f, ps1 = 0.f;
        #pragma unroll
        for (int nt = 0; nt < 8; nt++) {
            s[nt][0] = ex2f(s[nt][0] - mn0);
            s[nt][1] = ex2f(s[nt][1] - mn0);
            s[nt][2] = ex2f(s[nt][2] - mn1);
            s[nt][3] = ex2f(s[nt][3] - mn1);
            ps0 += s[nt][0] + s[nt][1];
            ps1 += s[nt][2] + s[nt][3];
        }
        ps0 += __shfl_xor_sync(0xffffffffu, ps0, 1);
        ps0 += __shfl_xor_sync(0xffffffffu, ps0, 2);
        ps1 += __shfl_xor_sync(0xffffffffu, ps1, 1);
        ps1 += __shfl_xor_sync(0xffffffffu, ps1, 2);
        lh0 = lh0 * c0 + ps0;
        lh1 = lh1 * c1 + ps1;
        #pragma unroll
        for (int nt = 0; nt < 8; nt++) {
            o[nt][0] *= c0; o[nt][1] *= c0;
            o[nt][2] *= c1; o[nt][3] *= c1;
        }

        // ---- write P (tf32) to warp-private SMEM slice ----
        {
            const int rowL0 = w * 16 + (lane >> 2);
            #pragma unroll
            for (int nt = 0; nt < 8; nt++) {
                int col = nt * 8 + 2 * (lane & 3);
                uint32_t base = (col >> 5) * 8192;
                uint32_t inoff = (col & 31) * 4;
                float2 p0; p0.x = to_tf32(s[nt][0]); p0.y = to_tf32(s[nt][1]);
                float2 p1; p1.x = to_tf32(s[nt][2]); p1.y = to_tf32(s[nt][3]);
                *(float2*)(smem + AT_P + base + sw128(rowL0 * 128 + inoff)) = p0;
                *(float2*)(smem + AT_P + base + sw128((rowL0 + 8) * 128 + inoff)) = p1;
            }
        }
        __syncwarp();

        // ---- O += P * V ----
        #pragma unroll
        for (int ks = 0; ks < 8; ks++) {
            uint32_t a0, a1, a2, a3;
            uint32_t aoff = (ks >> 2) * 8192 +
                            sw128(aRow * 128 + ((ks & 3) * 2 + aSegOff) * 16);
            ldsm_x4(sb + AT_P + aoff, a0, a1, a2, a3);
            #pragma unroll
            for (int pr = 0; pr < 4; pr++) {
                uint32_t boff = (ks >> 2) * 8192 +
                                sw128((pr * 16 + bRowL) * 128 + ((ks & 3) * 2 + bSegOff) * 16);
                uint32_t b0, b1, b2, b3;
                ldsm_x4(sV + boff, b0, b1, b2, b3);
                mma_tf32(o[pr*2][0], o[pr*2][1], o[pr*2][2], o[pr*2][3],
                         a0, a1, a2, a3, b0, b1);
                mma_tf32(o[pr*2+1][0], o[pr*2+1][1], o[pr*2+1][2], o[pr*2+1][3],
                         a0, a1, a2, a3, b2, b3);
            }
        }
        __syncthreads();
    }

    // ---- epilogue ----
    const float inv0 = (r0     > 0) ? 1.f / lh0 : 0.f;   // row 0 -> zeros
    const float inv1 = (r0 + 8 > 0) ? 1.f / lh1 : 0.f;
    const int b = bh >> 3, h = bh & 7;
    #pragma unroll
    for (int nt = 0; nt < 8; nt++) {
        const int d = h * DKH + nt * 8 + 2 * (lane & 3);
        float2 v0, v1;
        v0.x = to_tf32(o[nt][0] * inv0); v0.y = to_tf32(o[nt][1] * inv0);
        v1.x = to_tf32(o[nt][2] * inv1); v1.y = to_tf32(o[nt][3] * inv1);
        *(float2*)&out[((size_t)(b * SS + r0)) * DD + d] = v0;
        *(float2*)&out[((size_t)(b * SS + r0 + 8)) * DD + d] = v1;
    }
}

// ==================== transpose (+tf32 round): dst[C,R] = src[R,C]^T ========
__global__ __launch_bounds__(256) void transpose_kernel(const float* __restrict__ src,
                                                        float* __restrict__ dst,
                                                        int R, int C) {
    __shared__ float tile[32][33];
    const int c0 = blockIdx.x * 32, r0 = blockIdx.y * 32;
    const int x = threadIdx.x, y = threadIdx.y;
    #pragma unroll
    for (int j = 0; j < 32; j += 8)
        tile[y + j][x] = src[(size_t)(r0 + y + j) * C + c0 + x];
    __syncthreads();
    #pragma unroll
    for (int j = 0; j < 32; j += 8)
        dst[(size_t)(c0 + y + j) * R + r0 + x] = to_tf32(tile[x][y + j]);
}

// ---------------- out = in + pe; out_tf = tf32(out) -------------------------
__global__ __launch_bounds__(256) void addpe_kernel(const float* __restrict__ in,
                                                    const float* __restrict__ pe,
                                                    float* __restrict__ out,
                                                    float* __restrict__ out_tf) {
    int i4 = blockIdx.x * blockDim.x + threadIdx.x;
    const float4 a = ((const float4*)in)[i4];
    const float4 p = ((const float4*)pe)[i4 & (SS*DD/4 - 1)];
    float4 r; r.x=a.x+p.x; r.y=a.y+p.y; r.z=a.z+p.z; r.w=a.w+p.w;
    ((float4*)out)[i4] = r;
    float4 t; t.x=to_tf32(r.x); t.y=to_tf32(r.y); t.z=to_tf32(r.z); t.w=to_tf32(r.w);
    ((float4*)out_tf)[i4] = t;
}

// ---------------- layernorm: out = LN(a+b)*g+bt; out_tf = tf32(out) ---------
__global__ __launch_bounds__(128) void ln_kernel(const float* __restrict__ a,
                                                 const float* __restrict__ b,
                                                 const float* __restrict__ g,
                                                 const float* __restrict__ bt,
                                                 float* __restrict__ out,
                                                 float* __restrict__ out_tf) {
    __shared__ float red1[4], red2[4];
    const int r = blockIdx.x, t = threadIdx.x;
    const int w = t >> 5, l = t & 31;
    float4 za = *(const float4*)&a[(size_t)r * DD + t * 4];
    float4 zb = *(const float4*)&b[(size_t)r * DD + t * 4];
    float z0 = za.x + zb.x, z1 = za.y + zb.y, z2 = za.z + zb.z, z3 = za.w + zb.w;

    float s = z0 + z1 + z2 + z3;
    #pragma unroll
    for (int off = 16; off; off >>= 1) s += __shfl_xor_sync(0xffffffffu, s, off);
    if (l == 0) red1[w] = s;
    __syncthreads();
    const float mean = (red1[0] + red1[1] + red1[2] + red1[3]) * (1.f / DD);

    float d0 = z0 - mean, d1 = z1 - mean, d2 = z2 - mean, d3 = z3 - mean;
    float sq = d0*d0 + d1*d1 + d2*d2 + d3*d3;
    #pragma unroll
    for (int off = 16; off; off >>= 1) sq += __shfl_xor_sync(0xffffffffu, sq, off);
    if (l == 0) red2[w] = sq;
    __syncthreads();
    const float var = (red2[0] + red2[1] + red2[2] + red2[3]) * (1.f / DD);
    const float rstd = rsqrtf(var + 1e-5f);

    float4 gg = *(const float4*)&g[t * 4];
    float4 bb = *(const float4*)&bt[t * 4];
    float4 o;
    o.x = d0 * rstd * gg.x + bb.x;
    o.y = d1 * rstd * gg.y + bb.y;
    o.z = d2 * rstd * gg.z + bb.z;
    o.w = d3 * rstd * gg.w + bb.w;
    *(float4*)&out[(size_t)r * DD + t * 4] = o;
    float4 tf;
    tf.x = to_tf32(o.x); tf.y = to_tf32(o.y); tf.z = to_tf32(o.z); tf.w = to_tf32(o.w);
    *(float4*)&out_tf[(size_t)r * DD + t * 4] = tf;
}

// ---------------- orchestration ---------------------------------------------
extern "C" void kernel_launch(void* const* d_in, const int* in_sizes, int n_in,
                              void* d_out, int out_size) {
    const float* q_embed = (const float*)d_in[0];
    const float* qa_embed= (const float*)d_in[1];
    const float* pe      = (const float*)d_in[2];
    const float* Wk      = (const float*)d_in[3];
    const float* bk      = (const float*)d_in[4];
    const float* Wv      = (const float*)d_in[5];
    const float* bv      = (const float*)d_in[6];
    const float* Wo      = (const float*)d_in[7];
    const float* bo      = (const float*)d_in[8];
    const float* ln1_s   = (const float*)d_in[9];
    const float* ln1_b   = (const float*)d_in[10];
    const float* W1      = (const float*)d_in[11];
    const float* b1      = (const float*)d_in[12];
    const float* W2      = (const float*)d_in[13];
    const float* b2      = (const float*)d_in[14];
    const float* ln2_s   = (const float*)d_in[15];
    const float* ln2_b   = (const float*)d_in[16];
    float* outp = (float*)d_out;

    float *x, *xtf, *y, *x1, *x1tf, *qkb, *vtb, *att, *tmp, *hb;
    float *wkT, *wvT, *woT, *w1T, *w2T;
    cudaGetSymbolAddress((void**)&x,    g_x);
    cudaGetSymbolAddress((void**)&xtf,  g_xtf);
    cudaGetSymbolAddress((void**)&y,    g_y);
    cudaGetSymbolAddress((void**)&x1,   g_x1);
    cudaGetSymbolAddress((void**)&x1tf, g_x1tf);
    cudaGetSymbolAddress((void**)&qkb,  g_qk);
    cudaGetSymbolAddress((void**)&vtb,  g_vt);
    cudaGetSymbolAddress((void**)&att,  g_att);
    cudaGetSymbolAddress((void**)&tmp,  g_tmp);
    cudaGetSymbolAddress((void**)&hb,   g_h);
    cudaGetSymbolAddress((void**)&wkT,  g_wkT);
    cudaGetSymbolAddress((void**)&wvT,  g_wvT);
    cudaGetSymbolAddress((void**)&woT,  g_woT);
    cudaGetSymbolAddress((void**)&w1T,  g_w1T);
    cudaGetSymbolAddress((void**)&w2T,  g_w2T);

    cudaFuncSetAttribute(tc_gemm<0>, cudaFuncAttributeMaxDynamicSharedMemorySize, SM_TOTAL);
    cudaFuncSetAttribute(tc_gemm<1>, cudaFuncAttributeMaxDynamicSharedMemorySize, SM_TOTAL);
    cudaFuncSetAttribute(tc_gemm<2>, cudaFuncAttributeMaxDynamicSharedMemorySize, SM_TOTAL);
    cudaFuncSetAttribute(tc_gemm<3>, cudaFuncAttributeMaxDynamicSharedMemorySize, SM_TOTAL);
    cudaFuncSetAttribute(attn_tc,    cudaFuncAttributeMaxDynamicSharedMemorySize, AT_TOTAL);

    const int n4 = MROWS * DD / 4;
    addpe_kernel<<<n4 / 256, 256>>>(q_embed,  pe, x, xtf);
    addpe_kernel<<<n4 / 256, 256>>>(qa_embed, pe, y, y);   // y only used as GEMM A -> rounded

    dim3 tb(32, 8);
    dim3 gT_dd(DD / 32, DD / 32);
    dim3 gT_w1(DFF / 32, DD / 32);
    dim3 gT_w2(DD / 32, DFF / 32);

    dim3 gProj(DD / TILE_N,  MROWS / TILE_M);   // (4, 64)
    dim3 gFfn1(DFF / TILE_N, MROWS / TILE_M);   // (16, 64)
    dim3 gAttn(SS / 64, BB * HH);               // (16, 64)

    for (int l = 0; l < LL; l++) {
        const float* wk = Wk + (size_t)l * DD * DD;
        const float* wv = Wv + (size_t)l * DD * DD;
        const float* wo = Wo + (size_t)l * DD * DD;
        const float* w1 = W1 + (size_t)l * DD * DFF;
        const float* w2 = W2 + (size_t)l * DFF * DD;

        transpose_kernel<<<gT_dd, tb>>>(wk, wkT, DD, DD);
        transpose_kernel<<<gT_dd, tb>>>(wv, wvT, DD, DD);
        transpose_kernel<<<gT_dd, tb>>>(wo, woT, DD, DD);
        transpose_kernel<<<gT_w1, tb>>>(w1, w1T, DD, DFF);
        transpose_kernel<<<gT_w2, tb>>>(w2, w2T, DFF, DD);

        // q == k (kq_same): single projection
        tc_gemm<2><<<gProj, 256, SM_TOTAL>>>(xtf, wkT, bk + l * DD, qkb, MROWS, DD, DD);
        tc_gemm<3><<<gProj, 256, SM_TOTAL>>>(y,   wvT, bv + l * DD, vtb, MROWS, DD, DD);
        attn_tc<<<gAttn, 128, AT_TOTAL>>>(qkb, vtb, att);
        tc_gemm<0><<<gProj, 256, SM_TOTAL>>>(att, woT, bo + l * DD, tmp, MROWS, DD, DD);
        ln_kernel<<<MROWS, 128>>>(x, tmp, ln1_s + l * DD, ln1_b + l * DD, x1, x1tf);
        tc_gemm<1><<<gFfn1, 256, SM_TOTAL>>>(x1tf, w1T, b1 + l * DFF, hb, MROWS, DFF, DD);
        tc_gemm<0><<<gProj, 256, SM_TOTAL>>>(hb, w2T, b2 + l * DD, tmp, MROWS, DD, DFF);
        float* dst = (l == LL - 1) ? outp : x;
        ln_kernel<<<MROWS, 128>>>(x1, tmp, ln2_s + l * DD, ln2_b + l * DD, dst, xtf);
    }
}